// round 5
// baseline (speedup 1.0000x reference)
#include <cuda_runtime.h>

// Fixed problem shapes
#define BB 16
#define TT 288
#define NN 4096
#define HH 10
#define RR 16
#define TCHUNKS 8
#define TPC (TT / TCHUNKS)            // 36
#define XBLK 8                        // k1 blocks along n
#define NBLKS1 (XBLK * BB * TCHUNKS)  // 1024
#define K3QC 64                       // k3 q-chunks (32 q-pairs each)
#define NBLKS3 (K3QC * BB)            // 1024

// Scratch: fully rewritten each replay before reads; counter restored to 0.
__device__ float4 g_part[TCHUNKS][BB][NN / 2];  // (s0,c0,s1,c1) per node pair
__device__ float2 g_blk[NBLKS1];                // per-k1-block (sum, cnt)
__device__ float  g_gmean;
__device__ float  g_rcnt[RR];
__device__ float  g_regp[BB][K3QC][RR];         // regional partial sums
__device__ unsigned int g_ctr;                  // zero at load; restored each replay

// ---------------------------------------------------------------------------
// Kernel 1: the single heavy pass over 151MB (float4 streaming loads).
// grid (8,16,8) = 1024 blocks x 256 thr (one full wave at 8 blocks/SM).
// ---------------------------------------------------------------------------
__global__ void __launch_bounds__(256, 8) k1_main(const float4* __restrict__ data) {
    const int tid = threadIdx.x;
    const int b   = blockIdx.y;
    const int tc  = blockIdx.z;
    const int q   = blockIdx.x * 256 + tid;   // float4 column in [0, NN/2)

    const float4* __restrict__ p =
        data + (size_t)(b * TT + tc * TPC) * (NN / 2) + q;

    float s0 = 0.f, s1 = 0.f, c0 = 0.f, c1 = 0.f;
    #pragma unroll 6
    for (int t = 0; t < TPC; ++t) {
        float4 v = __ldcs(p);
        p += NN / 2;
        if (v.x != -1.0f) { s0 += v.x; c0 += 1.0f; }
        if (v.z != -1.0f) { s1 += v.z; c1 += 1.0f; }
    }
    g_part[tc][b][q] = make_float4(s0, c0, s1, c1);

    // Block-reduce (sum, cnt) -> g_blk
    float s = s0 + s1;
    float c = c0 + c1;
    #pragma unroll
    for (int o = 16; o > 0; o >>= 1) {
        s += __shfl_down_sync(0xffffffffu, s, o);
        c += __shfl_down_sync(0xffffffffu, c, o);
    }
    __shared__ float sh_s[8], sh_c[8];
    const int wid = tid >> 5, lane = tid & 31;
    if (lane == 0) { sh_s[wid] = s; sh_c[wid] = c; }
    __syncthreads();
    if (tid == 0) {
        s = 0.f; c = 0.f;
        #pragma unroll
        for (int w = 0; w < 8; ++w) { s += sh_s[w]; c += sh_c[w]; }
        const int bid = (blockIdx.z * BB + blockIdx.y) * XBLK + blockIdx.x;
        g_blk[bid] = make_float2(s, c);
    }
}

// ---------------------------------------------------------------------------
// Kernel 2: gmean (from 1024 block partials) + per-region node counts.
// 1 block x 1024 thr, ~24KB of reads.
// ---------------------------------------------------------------------------
__global__ void __launch_bounds__(1024) k2_gmean(const int* __restrict__ cid) {
    const int tid = threadIdx.x;

    __shared__ float rc[RR];
    if (tid < RR) rc[tid] = 0.f;
    __syncthreads();
    #pragma unroll
    for (int i = tid; i < NN; i += 1024)
        atomicAdd(&rc[cid[i]], 1.0f);

    float2 v = g_blk[tid];
    float s = v.x, c = v.y;
    #pragma unroll
    for (int o = 16; o > 0; o >>= 1) {
        s += __shfl_down_sync(0xffffffffu, s, o);
        c += __shfl_down_sync(0xffffffffu, c, o);
    }
    __shared__ float sh_s[32], sh_c[32];
    const int wid = tid >> 5, lane = tid & 31;
    if (lane == 0) { sh_s[wid] = s; sh_c[wid] = c; }
    __syncthreads();
    if (tid == 0) {
        s = 0.f; c = 0.f;
        #pragma unroll
        for (int w = 0; w < 32; ++w) { s += sh_s[w]; c += sh_c[w]; }
        g_gmean = s / fmaxf(c, 1.0f);
    }
    if (tid < RR) g_rcnt[tid] = rc[tid];
}

// ---------------------------------------------------------------------------
// Kernel 3: 8 threads per node-pair, one tc-slice each.
// grid (K3QC=64, BB=16) = 1024 blocks x 256 thr = 262144 threads.
// Per thread: 1 float4 load -> 3 shfl_xor -> compute mean -> 1-2 float2 stores.
// Regional partials via shared atomics (tc==0 threads only); tiny last-block
// tail writes the regional output.
// ---------------------------------------------------------------------------
__global__ void __launch_bounds__(256) k3_outputs(const int* __restrict__ cid,
                                                  float* __restrict__ out) {
    const int tid  = threadIdx.x;
    const int b    = blockIdx.y;
    const int lane = tid & 31;
    const int w    = tid >> 5;         // warp 0..7
    const int ql   = lane & 3;         // q within warp-group
    const int tc   = lane >> 2;        // 0..7
    const int q    = blockIdx.x * 32 + w * 4 + ql;   // node-pair index
    const int n0   = q * 2;

    __shared__ float rs[RR];
    if (tid < RR) rs[tid] = 0.f;
    __syncthreads();

    // one partial slice per thread
    float4 v = g_part[tc][b][q];
    float s0 = v.x, c0 = v.y, s1 = v.z, c1 = v.w;
    #pragma unroll
    for (int m = 4; m <= 16; m <<= 1) {
        s0 += __shfl_xor_sync(0xffffffffu, s0, m);
        c0 += __shfl_xor_sync(0xffffffffu, c0, m);
        s1 += __shfl_xor_sync(0xffffffffu, s1, m);
        c1 += __shfl_xor_sync(0xffffffffu, c1, m);
    }

    const float gm   = g_gmean;
    const float invT = 1.0f / (float)TT;
    const float m0 = (s0 + ((float)TT - c0) * gm) * invT;
    const float m1 = (s1 + ((float)TT - c1) * gm) * invT;
    const float2 mm = make_float2(m0, m1);

    // pred_speed: h = tc, and h = tc+8 for tc<2 (covers H=10)
    float2* __restrict__ o2 = (float2*)out;
    o2[((size_t)b * HH + tc) * (NN / 2) + q] = mm;
    if (tc < 2)
        o2[((size_t)b * HH + tc + 8) * (NN / 2) + q] = mm;

    // regional partials (one thread per node-pair)
    if (tc == 0) {
        const int2 cc = ((const int2*)cid)[q];
        atomicAdd(&rs[cc.x], m0);
        atomicAdd(&rs[cc.y], m1);
    }
    __syncthreads();
    if (tid < RR)
        g_regp[b][blockIdx.x][tid] = rs[tid];

    // ---- last-block-done: regional output ----
    __shared__ bool amLast;
    __syncthreads();
    if (tid == 0) {
        __threadfence();
        amLast = (atomicAdd(&g_ctr, 1u) == NBLKS3 - 1);
    }
    __syncthreads();
    if (!amLast) return;

    // tid -> (bb, r): sum 64 chunk partials, divide, tile over H
    const int bb = tid >> 4;
    const int r  = tid & 15;
    float acc = 0.f;
    #pragma unroll
    for (int x = 0; x < K3QC; ++x)
        acc += g_regp[bb][x][r];
    const float val = acc / fmaxf(g_rcnt[r], 1.0f);

    float* __restrict__ ro = out + (size_t)BB * HH * NN;
    #pragma unroll
    for (int h = 0; h < HH; ++h)
        ro[((size_t)bb * HH + h) * RR + r] = val;

    if (tid == 0) g_ctr = 0;   // restore for next graph replay
}

// ---------------------------------------------------------------------------
extern "C" void kernel_launch(void* const* d_in, const int* in_sizes, int n_in,
                              void* d_out, int out_size) {
    const float4* data = (const float4*)d_in[0];
    const int*    cid  = (const int*)d_in[1];
    float*        out  = (float*)d_out;

    dim3 g1(XBLK, BB, TCHUNKS);   // 1024 blocks
    k1_main<<<g1, 256>>>(data);
    k2_gmean<<<1, 1024>>>(cid);
    dim3 g3(K3QC, BB);            // 1024 blocks
    k3_outputs<<<g3, 256>>>(cid, out);
}